// round 7
// baseline (speedup 1.0000x reference)
#include <cuda_runtime.h>
#include <cstdint>

#define MD 2048
#define ND 8192
#define KD 30522
#define TK 32
#define SPC 0.001

#define HID_OFF   62509056LL   // 2048*30522
#define SCAL_OFF  79286272LL   // + 2048*8192

typedef unsigned long long u64;

// ---- device scratch (static globals; no allocations) ----
__device__ float  g_H[(size_t)MD * ND];   // encoder pre-activation
__device__ float  g_inv[ND];              // 1/row-norm of W_dec
__device__ int    g_ti[MD * TK];
__device__ float  g_tv[MD * TK];
__device__ double g_sse, g_sab;
__device__ int    g_act;

__global__ void k_init() { g_sse = 0.0; g_sab = 0.0; g_act = 0; }

// ---- packed f32x2 helpers (Blackwell FFMA2 pipe; PTX-only pattern) ----
__device__ __forceinline__ u64 dup2(float a) {
    u64 r; asm("mov.b64 %0,{%1,%1};" : "=l"(r) : "f"(a)); return r;
}
__device__ __forceinline__ float2 unp2(u64 v) {
    float2 r; asm("mov.b64 {%0,%1},%2;" : "=f"(r.x), "=f"(r.y) : "l"(v)); return r;
}
__device__ __forceinline__ void ffma2(u64& d, u64 a, u64 b) {
    asm("fma.rn.f32x2 %0,%1,%2,%0;" : "+l"(d) : "l"(a), "l"(b));
}
__device__ __forceinline__ void fadd2(u64& d, u64 a) {
    asm("add.rn.f32x2 %0,%0,%1;" : "+l"(d) : "l"(a));
}

// ================= encode GEMM: H = X @ W_enc + b_enc =================
// 128x128 tile, BK=8, 256 threads, 8x8 per thread held as 8x4 f32x2 pairs.
// Double-buffered smem; chunked accumulation (flush every 8 tiles = 64 K-terms)
// -> numerically identical to the validated scalar-FFMA version.
__global__ __launch_bounds__(256, 1) void k_enc(const float* __restrict__ X,
                                                const float* __restrict__ W,
                                                const float* __restrict__ B) {
    __shared__ float As[2][8][132];
    __shared__ float Bs[2][8][128];
    const int tid = threadIdx.x;
    const int m0 = blockIdx.y * 128, n0 = blockIdx.x * 128;
    const int arow = tid >> 1, ak = (tid & 1) * 4;   // A: 128 rows x 8 k
    const int bk = tid >> 5, bn = (tid & 31) * 4;    // B: 8 k x 128 n
    const int row0 = (tid >> 4) * 8, col0 = (tid & 15) * 8;
    const int KT = (KD + 7) / 8;                     // 3816 (= 8*477 exactly)

    float2 a0, a1; float4 bv;
    u64 ch[8][4], tt[8][4];                          // chunk + total, packed pairs
#pragma unroll
    for (int i = 0; i < 8; i++)
#pragma unroll
        for (int p = 0; p < 4; p++) { ch[i][p] = 0ull; tt[i][p] = 0ull; }

    auto loadT = [&](int t) {
        int gk = t * 8 + ak;
        const float* xp = X + (size_t)(m0 + arow) * KD + gk;
        a0 = (gk     < KD) ? *(const float2*)xp       : make_float2(0.f, 0.f);
        a1 = (gk + 2 < KD) ? *(const float2*)(xp + 2) : make_float2(0.f, 0.f);
        int gbk = t * 8 + bk;
        bv = (gbk < KD) ? *(const float4*)(W + (size_t)gbk * ND + n0 + bn)
                        : make_float4(0.f, 0.f, 0.f, 0.f);
    };
    auto storeT = [&](int b) {
        As[b][ak    ][arow] = a0.x; As[b][ak + 1][arow] = a0.y;
        As[b][ak + 2][arow] = a1.x; As[b][ak + 3][arow] = a1.y;
        *(float4*)&Bs[b][bk][bn] = bv;
    };

    loadT(0); storeT(0); __syncthreads();
    int buf = 0;
    for (int t = 0; t < KT; t++) {
        if (t + 1 < KT) loadT(t + 1);
#pragma unroll
        for (int k = 0; k < 8; k++) {
            float4 av0 = *(const float4*)&As[buf][k][row0];
            float4 av1 = *(const float4*)&As[buf][k][row0 + 4];
            const u64* bp = (const u64*)&Bs[buf][k][col0];  // 4 packed col-pairs
            u64 b0 = bp[0], b1 = bp[1], b2 = bp[2], b3 = bp[3];
            u64 ad[8] = {dup2(av0.x), dup2(av0.y), dup2(av0.z), dup2(av0.w),
                         dup2(av1.x), dup2(av1.y), dup2(av1.z), dup2(av1.w)};
#pragma unroll
            for (int i = 0; i < 8; i++) {
                ffma2(ch[i][0], ad[i], b0);
                ffma2(ch[i][1], ad[i], b1);
                ffma2(ch[i][2], ad[i], b2);
                ffma2(ch[i][3], ad[i], b3);
            }
        }
        if ((t & 7) == 7) {
#pragma unroll
            for (int i = 0; i < 8; i++)
#pragma unroll
                for (int p = 0; p < 4; p++) { fadd2(tt[i][p], ch[i][p]); ch[i][p] = 0ull; }
        }
        if (t + 1 < KT) storeT(buf ^ 1);
        __syncthreads();
        buf ^= 1;
    }
    float4 bb0 = *(const float4*)(B + n0 + col0);
    float4 bb1 = *(const float4*)(B + n0 + col0 + 4);
    float bb[8] = {bb0.x, bb0.y, bb0.z, bb0.w, bb1.x, bb1.y, bb1.z, bb1.w};
#pragma unroll
    for (int i = 0; i < 8; i++) {
        float r[8];
#pragma unroll
        for (int p = 0; p < 4; p++) {
            float2 v = unp2(tt[i][p]);
            r[2 * p] = v.x + bb[2 * p];
            r[2 * p + 1] = v.y + bb[2 * p + 1];
        }
        float* hp = g_H + (size_t)(m0 + row0 + i) * ND + n0 + col0;
        *(float4*)hp       = make_float4(r[0], r[1], r[2], r[3]);
        *(float4*)(hp + 4) = make_float4(r[4], r[5], r[6], r[7]);
    }
}

// ================= W_dec row norms =================
__global__ void k_norm(const float* __restrict__ Wd) {
    int r = blockIdx.x, tid = threadIdx.x;
    const float* p = Wd + (size_t)r * KD;
    float s = 0.f;
    for (int c = tid; c < KD; c += 256) { float w = p[c]; s = fmaf(w, w, s); }
    __shared__ float red[256];
    red[tid] = s; __syncthreads();
    for (int o = 128; o; o >>= 1) { if (tid < o) red[tid] += red[tid + o]; __syncthreads(); }
    if (tid == 0) g_inv[r] = 1.0f / fmaxf(sqrtf(red[0]), 1e-12f);
}

// ================= exact top-32 per row + hidden scatter + sparsity stats =================
__global__ __launch_bounds__(256, 1) void k_topk(float* __restrict__ out) {
    __shared__ unsigned sk[ND];
    __shared__ int scnt, sslot;
    __shared__ int seq[256], spre[256];
    __shared__ float sred[256];
    __shared__ int sredi[256];
    const int tid = threadIdx.x, row = blockIdx.x;
    const float* h = g_H + (size_t)row * ND;
    for (int j = tid; j < ND; j += 256) {
        unsigned b = __float_as_uint(h[j]);
        sk[j] = (b & 0x80000000u) ? ~b : (b | 0x80000000u);   // order-preserving key
    }
    __syncthreads();
    // binary search: T = key of the 32nd largest (max t with count(>=t) >= 32)
    unsigned T = 0u;
    for (int bit = 31; bit >= 0; bit--) {
        unsigned tr = T | (1u << bit);
        if (tid == 0) scnt = 0;
        __syncthreads();
        int c = 0;
        for (int j = tid; j < ND; j += 256) c += (sk[j] >= tr);
        for (int o = 16; o; o >>= 1) c += __shfl_down_sync(0xffffffffu, c, o);
        if ((tid & 31) == 0) atomicAdd(&scnt, c);
        __syncthreads();
        int tot = scnt;
        __syncthreads();
        if (tot >= TK) T = tr;
    }
    if (tid == 0) scnt = 0;
    __syncthreads();
    { int c = 0;
      for (int j = tid; j < ND; j += 256) c += (sk[j] > T);
      for (int o = 16; o; o >>= 1) c += __shfl_down_sync(0xffffffffu, c, o);
      if ((tid & 31) == 0) atomicAdd(&scnt, c); }
    __syncthreads();
    const int meq = TK - scnt;           // #equals to take (lowest indices, jax tie-break)
    int e = 0;
    for (int j = tid * 32; j < tid * 32 + 32; j++) e += (sk[j] == T);
    seq[tid] = e;
    if (tid == 0) sslot = 0;
    __syncthreads();
    if (tid == 0) { int r = 0; for (int i = 0; i < 256; i++) { spre[i] = r; r += seq[i]; } }
    __syncthreads();
    float sab = 0.f; int act = 0;
    int run = spre[tid];
    float* ho = out + HID_OFF + (size_t)row * ND;
    for (int j = tid * 32; j < tid * 32 + 32; j++) {
        unsigned k = sk[j];
        bool sel = false;
        if (k > T) sel = true;
        else if (k == T) { sel = (run < meq); run++; }
        unsigned vb = (k & 0x80000000u) ? (k ^ 0x80000000u) : ~k;
        float v = __uint_as_float(vb);
        ho[j] = sel ? v : 0.f;
        if (sel) {
            int s = atomicAdd(&sslot, 1);
            g_ti[row * TK + s] = j; g_tv[row * TK + s] = v;
            sab += fabsf(v);
            act += (fabsf(v) > 1e-6f) ? 1 : 0;
        }
    }
    sred[tid] = sab; sredi[tid] = act; __syncthreads();
    for (int o = 128; o; o >>= 1) {
        if (tid < o) { sred[tid] += sred[tid + o]; sredi[tid] += sredi[tid + o]; }
        __syncthreads();
    }
    if (tid == 0) { atomicAdd(&g_sab, (double)sred[0]); atomicAdd(&g_act, sredi[0]); }
}

// ======== decode: recon = hidden @ (Wd/||row||) + b_dec, + SSE ========
// Column-tiled (16 tiles): grid x = rows (launch-order fastest), y = col tile.
// Working set per tile ~62 MB < L2 -> W_dec's 8x row reuse is captured in L2.
#define NTILE 16
#define CT 1908          // 16*1908 = 30528 >= KD; last tile has 1902 cols (even)
__global__ __launch_bounds__(256, 1) void k_dec(const float* __restrict__ X,
                                                const float* __restrict__ Wd,
                                                const float* __restrict__ Bd,
                                                float* __restrict__ out) {
    __shared__ float sv[TK];
    __shared__ size_t so[TK];
    __shared__ float fr[256];
    const int tid = threadIdx.x, row = blockIdx.x;
    const int c0 = blockIdx.y * CT;
    const int cend = min(c0 + CT, KD);
    if (tid < TK) {
        int id = g_ti[row * TK + tid];
        sv[tid] = g_tv[row * TK + tid] * g_inv[id];
        so[tid] = (size_t)id * KD;
    }
    __syncthreads();
    const float* xr = X + (size_t)row * KD;
    float* rr = out + (size_t)row * KD;
    float sse = 0.f;
    for (int c = c0 + tid * 2; c < cend; c += 512) {   // float2: 8B-aligned (c even, KD even)
        float2 acc = *(const float2*)(Bd + c);
#pragma unroll
        for (int t = 0; t < TK; t++) {
            float2 w = *(const float2*)(Wd + so[t] + c);
            acc.x = fmaf(sv[t], w.x, acc.x);
            acc.y = fmaf(sv[t], w.y, acc.y);
        }
        float2 xv = *(const float2*)(xr + c);
        float dx = acc.x - xv.x, dy = acc.y - xv.y;
        sse = fmaf(dx, dx, sse); sse = fmaf(dy, dy, sse);
        *(float2*)(rr + c) = acc;
    }
    fr[tid] = sse; __syncthreads();
    for (int o = 128; o; o >>= 1) { if (tid < o) fr[tid] += fr[tid + o]; __syncthreads(); }
    if (tid == 0) atomicAdd(&g_sse, (double)fr[0]);
}

__global__ void k_fin(float* out) {
    double rec = g_sse / ((double)MD * KD);
    double sp  = SPC * (g_sab / ((double)MD * ND));
    out[SCAL_OFF + 0] = (float)(rec + sp);
    out[SCAL_OFF + 1] = (float)rec;
    out[SCAL_OFF + 2] = (float)sp;
    out[SCAL_OFF + 3] = (float)g_act / (float)MD;
}

extern "C" void kernel_launch(void* const* d_in, const int* in_sizes, int n_in,
                              void* d_out, int out_size) {
    const float* x  = (const float*)d_in[0];
    const float* We = (const float*)d_in[1];
    const float* be = (const float*)d_in[2];
    const float* Wd = (const float*)d_in[3];
    const float* bd = (const float*)d_in[4];
    float* out = (float*)d_out;

    k_init<<<1, 1>>>();
    k_norm<<<ND, 256>>>(Wd);
    dim3 g1(ND / 128, MD / 128);          // 64 x 16
    k_enc<<<g1, 256>>>(x, We, be);
    k_topk<<<MD, 256>>>(out);
    dim3 g2(MD, NTILE);
    k_dec<<<g2, 256>>>(x, Wd, bd, out);
    k_fin<<<1, 1>>>(out);
}